// round 1
// baseline (speedup 1.0000x reference)
#include <cuda_runtime.h>

// Problem constants
#define B_SZ   8192
#define D_IN   1024
#define D_OUT  4096
#define S_SEEDS 64
#define C_CH   64
#define H_HID  128

// Tiling
#define BM 128          // rows per block
#define KT 32           // k-tile for base GEMM
#define NTHREADS 256

// Shared memory layout (floats):
//   y_s   [C_CH][132]   = 8448   (y tile, k-major for stage A, kept for blend)
//   h_s   [H_HID][132]  = 16896  (hidden, k-major for stage B)
//   region (reused):
//      GEMM1:  x_s [KT][132] = 4224,  wb_s [KT][68] = 2176   (total 6400)
//      stageA: w1_s [C_CH][132] = 8448
//      stageB: w2_s [H_HID][68] = 8704
//   region size = 8704
#define YS_F    (C_CH * 132)
#define HS_F    (H_HID * 132)
#define REG_F   (H_HID * 68)
#define SMEM_FLOATS (YS_F + HS_F + REG_F)
#define SMEM_BYTES  (SMEM_FLOATS * 4)

__global__ __launch_bounds__(NTHREADS, 1)
void kasmina_fused_kernel(const float* __restrict__ x,
                          const float* __restrict__ Wb,
                          const float* __restrict__ bb,
                          const float* __restrict__ W1,
                          const float* __restrict__ b1,
                          const float* __restrict__ W2,
                          const float* __restrict__ b2,
                          const float* __restrict__ alpha,
                          const int*   __restrict__ active,
                          float* __restrict__ out)
{
    extern __shared__ float smem[];
    float* y_s  = smem;                 // [64][132]
    float* h_s  = smem + YS_F;          // [128][132]
    float* reg  = smem + YS_F + HS_F;   // reused region
    float* x_s  = reg;                  // [32][132]
    float* wb_s = reg + KT * 132;       // [32][68]
    float* w1_s = reg;                  // [64][132]
    float* w2_s = reg;                  // [128][68]

    const int s      = blockIdx.x;      // seed (fastest -> consecutive blocks share x rows in L2)
    const int row0   = blockIdx.y * BM;

    const int tid = threadIdx.x;
    const int ty  = tid >> 4;   // 0..15  -> rows ty*8 .. ty*8+7
    const int tx  = tid & 15;   // 0..15  -> cols tx*4 .. tx*4+3

    const float* xg = x  + (size_t)row0 * D_IN;
    const float* wg = Wb + (size_t)s * C_CH * D_IN;

    // ---------------- Stage 0: base GEMM  y = x_tile @ Wb_s^T ----------------
    float acc[8][4];
    #pragma unroll
    for (int i = 0; i < 8; i++)
        #pragma unroll
        for (int j = 0; j < 4; j++) acc[i][j] = 0.f;

    for (int k0 = 0; k0 < D_IN; k0 += KT) {
        // load x tile [BM x KT] -> x_s[k][row]  (transpose; coalesced GMEM reads)
        #pragma unroll
        for (int i = 0; i < 16; i++) {
            int idx = tid + i * NTHREADS;      // 0..4095
            int r = idx >> 5, k = idx & 31;
            x_s[k * 132 + r] = xg[(size_t)r * D_IN + k0 + k];
        }
        // load Wb tile [C_CH x KT] -> wb_s[k][n]
        #pragma unroll
        for (int i = 0; i < 8; i++) {
            int idx = tid + i * NTHREADS;      // 0..2047
            int n = idx >> 5, k = idx & 31;
            wb_s[k * 68 + n] = wg[(size_t)n * D_IN + k0 + k];
        }
        __syncthreads();

        #pragma unroll
        for (int kk = 0; kk < KT; kk++) {
            float4 a0 = *(const float4*)&x_s[kk * 132 + ty * 8];
            float4 a1 = *(const float4*)&x_s[kk * 132 + ty * 8 + 4];
            float4 bv = *(const float4*)&wb_s[kk * 68 + tx * 4];
            float av[8] = {a0.x, a0.y, a0.z, a0.w, a1.x, a1.y, a1.z, a1.w};
            float bw[4] = {bv.x, bv.y, bv.z, bv.w};
            #pragma unroll
            for (int i = 0; i < 8; i++)
                #pragma unroll
                for (int j = 0; j < 4; j++)
                    acc[i][j] = fmaf(av[i], bw[j], acc[i][j]);
        }
        __syncthreads();
    }

    // add base bias, stash y into y_s[c][row] (k-major for stage A)
    {
        float bias[4];
        #pragma unroll
        for (int j = 0; j < 4; j++) bias[j] = bb[s * C_CH + tx * 4 + j];
        #pragma unroll
        for (int j = 0; j < 4; j++) {
            float4 v0 = make_float4(acc[0][j] + bias[j], acc[1][j] + bias[j],
                                    acc[2][j] + bias[j], acc[3][j] + bias[j]);
            float4 v1 = make_float4(acc[4][j] + bias[j], acc[5][j] + bias[j],
                                    acc[6][j] + bias[j], acc[7][j] + bias[j]);
            *(float4*)&y_s[(tx * 4 + j) * 132 + ty * 8]     = v0;
            *(float4*)&y_s[(tx * 4 + j) * 132 + ty * 8 + 4] = v1;
        }
    }
    __syncthreads();

    // ---------------- Stage A: h = relu(y @ W1_s + b1) ----------------
    // load W1_s [C_CH x H_HID] -> w1_s[c][h]   (aliases x_s/wb_s region — GEMM1 done)
    {
        const float* w1g = W1 + (size_t)s * C_CH * H_HID;
        #pragma unroll
        for (int i = 0; i < 32; i++) {
            int idx = tid + i * NTHREADS;       // 0..8191
            int c = idx >> 7, h = idx & 127;
            w1_s[c * 132 + h] = w1g[c * H_HID + h];
        }
    }
    __syncthreads();

    #pragma unroll
    for (int nh = 0; nh < 2; nh++) {          // two 64-col halves of H
        float accH[8][4];
        #pragma unroll
        for (int i = 0; i < 8; i++)
            #pragma unroll
            for (int j = 0; j < 4; j++) accH[i][j] = 0.f;

        #pragma unroll 8
        for (int k = 0; k < C_CH; k++) {
            float4 a0 = *(const float4*)&y_s[k * 132 + ty * 8];
            float4 a1 = *(const float4*)&y_s[k * 132 + ty * 8 + 4];
            float4 bv = *(const float4*)&w1_s[k * 132 + nh * 64 + tx * 4];
            float av[8] = {a0.x, a0.y, a0.z, a0.w, a1.x, a1.y, a1.z, a1.w};
            float bw[4] = {bv.x, bv.y, bv.z, bv.w};
            #pragma unroll
            for (int i = 0; i < 8; i++)
                #pragma unroll
                for (int j = 0; j < 4; j++)
                    accH[i][j] = fmaf(av[i], bw[j], accH[i][j]);
        }
        // bias + relu, store h_s[hcol][row]
        #pragma unroll
        for (int j = 0; j < 4; j++) {
            int hcol = nh * 64 + tx * 4 + j;
            float bias = b1[s * H_HID + hcol];
            float v[8];
            #pragma unroll
            for (int i = 0; i < 8; i++) {
                float t = accH[i][j] + bias;
                v[i] = t > 0.f ? t : 0.f;
            }
            *(float4*)&h_s[hcol * 132 + ty * 8]     = make_float4(v[0], v[1], v[2], v[3]);
            *(float4*)&h_s[hcol * 132 + ty * 8 + 4] = make_float4(v[4], v[5], v[6], v[7]);
        }
    }
    __syncthreads();

    // ---------------- Stage B: bp = h @ W2_s + b2, then blend ----------------
    // load W2_s [H_HID x C_CH] -> w2_s[h][c]  (aliases w1_s region — stage A done)
    {
        const float* w2g = W2 + (size_t)s * H_HID * C_CH;
        #pragma unroll
        for (int i = 0; i < 32; i++) {
            int idx = tid + i * NTHREADS;       // 0..8191
            int h = idx >> 6, c = idx & 63;
            w2_s[h * 68 + c] = w2g[h * C_CH + c];
        }
    }
    __syncthreads();

    float accB[8][4];
    #pragma unroll
    for (int i = 0; i < 8; i++)
        #pragma unroll
        for (int j = 0; j < 4; j++) accB[i][j] = 0.f;

    #pragma unroll 8
    for (int k = 0; k < H_HID; k++) {
        float4 a0 = *(const float4*)&h_s[k * 132 + ty * 8];
        float4 a1 = *(const float4*)&h_s[k * 132 + ty * 8 + 4];
        float4 bv = *(const float4*)&w2_s[k * 68 + tx * 4];
        float av[8] = {a0.x, a0.y, a0.z, a0.w, a1.x, a1.y, a1.z, a1.w};
        float bw[4] = {bv.x, bv.y, bv.z, bv.w};
        #pragma unroll
        for (int i = 0; i < 8; i++)
            #pragma unroll
            for (int j = 0; j < 4; j++)
                accB[i][j] = fmaf(av[i], bw[j], accB[i][j]);
    }

    // blend + store
    {
        const float a_s = alpha[s] * (active[s] != 0 ? 1.f : 0.f);
        const float one_m_a = 1.f - a_s;
        float b2v[4];
        #pragma unroll
        for (int j = 0; j < 4; j++) b2v[j] = b2[s * C_CH + tx * 4 + j];

        #pragma unroll
        for (int i = 0; i < 8; i++) {
            int row = ty * 8 + i;
            float4 o;
            float vals[4];
            #pragma unroll
            for (int j = 0; j < 4; j++) {
                int col = tx * 4 + j;
                float yv = y_s[col * 132 + row];
                float bp = accB[i][j] + b2v[j];
                vals[j] = one_m_a * yv + a_s * bp;
            }
            o = make_float4(vals[0], vals[1], vals[2], vals[3]);
            *(float4*)&out[(size_t)(row0 + row) * D_OUT + s * C_CH + tx * 4] = o;
        }
    }
}

extern "C" void kernel_launch(void* const* d_in, const int* in_sizes, int n_in,
                              void* d_out, int out_size)
{
    const float* x     = (const float*)d_in[0];
    const float* Wb    = (const float*)d_in[1];
    const float* bb    = (const float*)d_in[2];
    const float* W1    = (const float*)d_in[3];
    const float* b1    = (const float*)d_in[4];
    const float* W2    = (const float*)d_in[5];
    const float* b2    = (const float*)d_in[6];
    const float* alpha = (const float*)d_in[7];
    const int*   active= (const int*)d_in[8];
    float* out = (float*)d_out;

    cudaFuncSetAttribute(kasmina_fused_kernel,
                         cudaFuncAttributeMaxDynamicSharedMemorySize, SMEM_BYTES);

    dim3 grid(S_SEEDS, B_SZ / BM);   // seed fastest -> x row-tile reuse in L2
    kasmina_fused_kernel<<<grid, NTHREADS, SMEM_BYTES>>>(
        x, Wb, bb, W1, b1, W2, b2, alpha, active, out);
}

// round 2
// speedup vs baseline: 2.7763x; 2.7763x over previous
#include <cuda_runtime.h>
#include <cstdint>

#define B_SZ   8192
#define D_IN   1024
#define D_OUT  4096
#define NTH    256

// ---- shared memory layout (bytes) ----
// y_f32:   [128][132] fp32                        -> 67584 (persistent)
// scratch: base loop { x_s 16KB @0, wb_s 16KB @16K }
//          epilogue  { w1_s 32KB @0, w2_s 32KB @32K, h_s 64KB @64K }
#define Y_OFF    0
#define Y_STRIDE 132              // floats per row
#define SCR      (128*Y_STRIDE*4) // 67584
#define XS_OFF   SCR
#define WBS_OFF  (SCR + 16384)
#define W1_OFF   SCR
#define W2_OFF   (SCR + 32768)
#define H_OFF    (SCR + 65536)
#define SMEM_TOTAL (SCR + 131072) // 198656

__device__ __forceinline__ uint32_t f2tf(float f) {
    uint32_t u; asm("cvt.rna.tf32.f32 %0, %1;" : "=r"(u) : "f"(f)); return u;
}
__device__ __forceinline__ void ldsm4(uint32_t& r0, uint32_t& r1, uint32_t& r2,
                                      uint32_t& r3, uint32_t addr) {
    asm volatile("ldmatrix.sync.aligned.m8n8.x4.shared.b16 {%0,%1,%2,%3}, [%4];"
                 : "=r"(r0), "=r"(r1), "=r"(r2), "=r"(r3) : "r"(addr));
}
__device__ __forceinline__ void mma8(float* c, const uint32_t* a, const uint32_t* b) {
    asm volatile("mma.sync.aligned.m16n8k8.row.col.f32.tf32.tf32.f32 "
                 "{%0,%1,%2,%3},{%4,%5,%6,%7},{%8,%9},{%0,%1,%2,%3};"
                 : "+f"(c[0]), "+f"(c[1]), "+f"(c[2]), "+f"(c[3])
                 : "r"(a[0]), "r"(a[1]), "r"(a[2]), "r"(a[3]),
                   "r"(b[0]), "r"(b[1]));
}

__global__ __launch_bounds__(NTH, 1)
void kasmina_mma_kernel(const float* __restrict__ x,
                        const float* __restrict__ Wb,
                        const float* __restrict__ bb,
                        const float* __restrict__ W1,
                        const float* __restrict__ b1,
                        const float* __restrict__ W2,
                        const float* __restrict__ b2,
                        const float* __restrict__ alpha,
                        const int*   __restrict__ active,
                        float* __restrict__ out)
{
    extern __shared__ char smem[];
    const uint32_t smem_u = (uint32_t)__cvta_generic_to_shared(smem);
    float* ysm = (float*)(smem + Y_OFF);

    const int sp   = blockIdx.x;          // seed-pair: out cols [sp*128, sp*128+128)
    const int row0 = blockIdx.y * 128;

    const int tid    = threadIdx.x;
    const int lane   = tid & 31;
    const int wid    = tid >> 5;
    const int warp_m = wid & 1;           // 64-row half
    const int warp_n = wid >> 1;          // 32-col quarter

    const float* xg  = x  + (size_t)row0 * D_IN;
    const float* wbg = Wb + (size_t)(sp * 128) * D_IN;

    // ================= base GEMM: y = x @ Wb_slice^T =================
    float acc[4][4][4];
    #pragma unroll
    for (int mt = 0; mt < 4; mt++)
        #pragma unroll
        for (int nt = 0; nt < 4; nt++)
            #pragma unroll
            for (int q = 0; q < 4; q++) acc[mt][nt][q] = 0.f;

    const uint32_t xs_b  = smem_u + XS_OFF;
    const uint32_t wbs_b = smem_u + WBS_OFF;

    for (int ks = 0; ks < 32; ks++) {
        const int k0 = ks * 32;
        // stage x tile [128 x 32] (tf32, swizzled)
        #pragma unroll
        for (int i = 0; i < 4; i++) {
            int idx = tid + i * NTH;
            int r = idx >> 3, c4 = idx & 7;
            float4 v = *(const float4*)(xg + (size_t)r * D_IN + k0 + c4 * 4);
            uint4 u = make_uint4(f2tf(v.x), f2tf(v.y), f2tf(v.z), f2tf(v.w));
            *(uint4*)(smem + XS_OFF + r * 128 + ((c4 ^ (r & 7)) << 4)) = u;
        }
        // stage Wb tile [128 x 32]
        #pragma unroll
        for (int i = 0; i < 4; i++) {
            int idx = tid + i * NTH;
            int n = idx >> 3, c4 = idx & 7;
            float4 v = *(const float4*)(wbg + (size_t)n * D_IN + k0 + c4 * 4);
            uint4 u = make_uint4(f2tf(v.x), f2tf(v.y), f2tf(v.z), f2tf(v.w));
            *(uint4*)(smem + WBS_OFF + n * 128 + ((c4 ^ (n & 7)) << 4)) = u;
        }
        __syncthreads();

        #pragma unroll
        for (int kk = 0; kk < 4; kk++) {
            uint32_t a[4][4], b[4][2];
            #pragma unroll
            for (int mt = 0; mt < 4; mt++) {
                int row = warp_m * 64 + mt * 16 + ((lane >> 3) & 1) * 8 + (lane & 7);
                int hi  = lane >> 4;
                uint32_t ad = xs_b + row * 128 + ((((kk << 1) | hi) ^ (row & 7)) << 4);
                ldsm4(a[mt][0], a[mt][1], a[mt][2], a[mt][3], ad);
            }
            #pragma unroll
            for (int p = 0; p < 2; p++) {
                int row = warp_n * 32 + p * 16 + (lane >> 4) * 8 + (lane & 7);
                int hi  = (lane >> 3) & 1;
                uint32_t ad = wbs_b + row * 128 + ((((kk << 1) | hi) ^ (row & 7)) << 4);
                ldsm4(b[2*p][0], b[2*p][1], b[2*p+1][0], b[2*p+1][1], ad);
            }
            #pragma unroll
            for (int mt = 0; mt < 4; mt++)
                #pragma unroll
                for (int nt = 0; nt < 4; nt++)
                    mma8(acc[mt][nt], a[mt], b[nt]);
        }
        __syncthreads();
    }

    // base epilogue: y = acc + bb -> smem (fp32)
    #pragma unroll
    for (int mt = 0; mt < 4; mt++) {
        #pragma unroll
        for (int nt = 0; nt < 4; nt++) {
            int c0 = warp_n * 32 + nt * 8 + 2 * (lane & 3);
            float2 bbv = *(const float2*)&bb[sp * 128 + c0];
            int r0 = warp_m * 64 + mt * 16 + (lane >> 2);
            *(float2*)&ysm[r0 * Y_STRIDE + c0] =
                make_float2(acc[mt][nt][0] + bbv.x, acc[mt][nt][1] + bbv.y);
            *(float2*)&ysm[(r0 + 8) * Y_STRIDE + c0] =
                make_float2(acc[mt][nt][2] + bbv.x, acc[mt][nt][3] + bbv.y);
        }
    }

    const uint32_t w1_b = smem_u + W1_OFF;
    const uint32_t w2_b = smem_u + W2_OFF;
    const uint32_t h_b  = smem_u + H_OFF;

    // ================= per-seed MLP + blend =================
    #pragma unroll 1
    for (int sl = 0; sl < 2; sl++) {
        const int sg = sp * 2 + sl;

        // load W1^T [h][c] and W2^T [c][h] as tf32, swizzled
        {
            const float* w1g = W1 + (size_t)sg * 64 * 128;
            #pragma unroll
            for (int i = 0; i < 32; i++) {
                int idx = tid + i * NTH;     // 0..8191
                int c = idx >> 7, h = idx & 127;
                uint32_t v = f2tf(w1g[c * 128 + h]);
                *(uint32_t*)(smem + W1_OFF + h * 256 +
                             (((c >> 2) ^ (h & 7)) << 4) + (c & 3) * 4) = v;
            }
            const float* w2g = W2 + (size_t)sg * 128 * 64;
            #pragma unroll
            for (int i = 0; i < 32; i++) {
                int idx = tid + i * NTH;
                int h = idx >> 6, c = idx & 63;
                uint32_t v = f2tf(w2g[h * 64 + c]);
                *(uint32_t*)(smem + W2_OFF + c * 512 +
                             (((h >> 2) ^ (c & 7)) << 4) + (h & 3) * 4) = v;
            }
        }
        __syncthreads();

        // ---- stage A: h = relu(y_tf32 @ W1 + b1) ----  M=128 N=128 K=64
        {
            float accA[4][4][4];
            #pragma unroll
            for (int mt = 0; mt < 4; mt++)
                #pragma unroll
                for (int nt = 0; nt < 4; nt++)
                    #pragma unroll
                    for (int q = 0; q < 4; q++) accA[mt][nt][q] = 0.f;

            #pragma unroll 2
            for (int kk = 0; kk < 8; kk++) {
                uint32_t a[4][4], b[4][2];
                int colb = sl * 64 + kk * 8 + (lane & 3);
                #pragma unroll
                for (int mt = 0; mt < 4; mt++) {
                    int r0 = warp_m * 64 + mt * 16 + (lane >> 2);
                    a[mt][0] = f2tf(ysm[r0 * Y_STRIDE + colb]);
                    a[mt][1] = f2tf(ysm[(r0 + 8) * Y_STRIDE + colb]);
                    a[mt][2] = f2tf(ysm[r0 * Y_STRIDE + colb + 4]);
                    a[mt][3] = f2tf(ysm[(r0 + 8) * Y_STRIDE + colb + 4]);
                }
                #pragma unroll
                for (int p = 0; p < 2; p++) {
                    int row = warp_n * 32 + p * 16 + (lane >> 4) * 8 + (lane & 7);
                    int hi  = (lane >> 3) & 1;
                    uint32_t ad = w1_b + row * 256 + ((((kk << 1) | hi) ^ (row & 7)) << 4);
                    ldsm4(b[2*p][0], b[2*p][1], b[2*p+1][0], b[2*p+1][1], ad);
                }
                #pragma unroll
                for (int mt = 0; mt < 4; mt++)
                    #pragma unroll
                    for (int nt = 0; nt < 4; nt++)
                        mma8(accA[mt][nt], a[mt], b[nt]);
            }

            // bias + relu + cvt -> h_s
            #pragma unroll
            for (int mt = 0; mt < 4; mt++) {
                #pragma unroll
                for (int nt = 0; nt < 4; nt++) {
                    int h0 = warp_n * 32 + nt * 8 + 2 * (lane & 3);
                    float2 b1v = *(const float2*)&b1[sg * 128 + h0];
                    int r0 = warp_m * 64 + mt * 16 + (lane >> 2);
                    float v0 = fmaxf(accA[mt][nt][0] + b1v.x, 0.f);
                    float v1 = fmaxf(accA[mt][nt][1] + b1v.y, 0.f);
                    float v2 = fmaxf(accA[mt][nt][2] + b1v.x, 0.f);
                    float v3 = fmaxf(accA[mt][nt][3] + b1v.y, 0.f);
                    uint32_t swz = (((h0 >> 2) ^ (r0 & 7)) << 4) + (h0 & 3) * 4;
                    *(uint2*)(smem + H_OFF + r0 * 512 + swz) =
                        make_uint2(f2tf(v0), f2tf(v1));
                    *(uint2*)(smem + H_OFF + (r0 + 8) * 512 + swz) =
                        make_uint2(f2tf(v2), f2tf(v3));
                }
            }
        }
        __syncthreads();

        // ---- stage B: bp = h @ W2 + b2; blend; store ----  M=128 N=64 K=128
        {
            float accB[4][2][4];
            #pragma unroll
            for (int mt = 0; mt < 4; mt++)
                #pragma unroll
                for (int nt = 0; nt < 2; nt++)
                    #pragma unroll
                    for (int q = 0; q < 4; q++) accB[mt][nt][q] = 0.f;

            #pragma unroll 4
            for (int kk = 0; kk < 16; kk++) {
                uint32_t a[4][4], b[2][2];
                #pragma unroll
                for (int mt = 0; mt < 4; mt++) {
                    int row = warp_m * 64 + mt * 16 + ((lane >> 3) & 1) * 8 + (lane & 7);
                    int hi  = lane >> 4;
                    uint32_t ad = h_b + row * 512 + ((((kk << 1) | hi) ^ (row & 7)) << 4);
                    ldsm4(a[mt][0], a[mt][1], a[mt][2], a[mt][3], ad);
                }
                {
                    int row = warp_n * 16 + (lane >> 4) * 8 + (lane & 7);
                    int hi  = (lane >> 3) & 1;
                    uint32_t ad = w2_b + row * 512 + ((((kk << 1) | hi) ^ (row & 7)) << 4);
                    ldsm4(b[0][0], b[0][1], b[1][0], b[1][1], ad);
                }
                #pragma unroll
                for (int mt = 0; mt < 4; mt++)
                    #pragma unroll
                    for (int nt = 0; nt < 2; nt++)
                        mma8(accB[mt][nt], a[mt], b[nt]);
            }

            const float aw  = alpha[sg] * (active[sg] != 0 ? 1.f : 0.f);
            const float omw = 1.f - aw;
            #pragma unroll
            for (int mt = 0; mt < 4; mt++) {
                #pragma unroll
                for (int nt = 0; nt < 2; nt++) {
                    int c0 = warp_n * 16 + nt * 8 + 2 * (lane & 3);
                    float2 b2v = *(const float2*)&b2[sg * 64 + c0];
                    int r0 = warp_m * 64 + mt * 16 + (lane >> 2);

                    float2 y0 = *(const float2*)&ysm[r0 * Y_STRIDE + sl * 64 + c0];
                    float o0 = omw * y0.x + aw * (accB[mt][nt][0] + b2v.x);
                    float o1 = omw * y0.y + aw * (accB[mt][nt][1] + b2v.y);
                    *(float2*)&out[(size_t)(row0 + r0) * D_OUT + sg * 64 + c0] =
                        make_float2(o0, o1);

                    float2 y1 = *(const float2*)&ysm[(r0 + 8) * Y_STRIDE + sl * 64 + c0];
                    float o2 = omw * y1.x + aw * (accB[mt][nt][2] + b2v.x);
                    float o3 = omw * y1.y + aw * (accB[mt][nt][3] + b2v.y);
                    *(float2*)&out[(size_t)(row0 + r0 + 8) * D_OUT + sg * 64 + c0] =
                        make_float2(o2, o3);
                }
            }
        }
        __syncthreads();
    }
}

extern "C" void kernel_launch(void* const* d_in, const int* in_sizes, int n_in,
                              void* d_out, int out_size)
{
    const float* x      = (const float*)d_in[0];
    const float* Wb     = (const float*)d_in[1];
    const float* bb     = (const float*)d_in[2];
    const float* W1     = (const float*)d_in[3];
    const float* b1     = (const float*)d_in[4];
    const float* W2     = (const float*)d_in[5];
    const float* b2     = (const float*)d_in[6];
    const float* alpha  = (const float*)d_in[7];
    const int*   active = (const int*)d_in[8];
    float* out = (float*)d_out;

    cudaFuncSetAttribute(kasmina_mma_kernel,
                         cudaFuncAttributeMaxDynamicSharedMemorySize, SMEM_TOTAL);

    dim3 grid(32, 64);   // (seed pairs, row blocks); seed fastest for x L2 reuse
    kasmina_mma_kernel<<<grid, NTH, SMEM_TOTAL>>>(
        x, Wb, bb, W1, b1, W2, b2, alpha, active, out);
}

// round 4
// speedup vs baseline: 4.4043x; 1.5864x over previous
#include <cuda_runtime.h>
#include <cstdint>

#define NTH    256
#define D_IN   1024
#define D_OUT  4096

#define XN   (8192 * 1024)
#define WBN  (4096 * 1024)
#define WIMG (64 * 8192)          // 64 seeds x 8192 u32 (32KB image each)

__device__ uint32_t g_xt[XN];     // x as tf32 bits
__device__ uint32_t g_wbt[WBN];   // Wb as tf32 bits
__device__ uint32_t g_w1img[WIMG]; // W1 pre-swizzled smem images
__device__ uint32_t g_w2img[WIMG]; // W2 pre-swizzled smem images

// ---------------- smem layout (bytes) ----------------
// phase 1: 4 staging buffers, 32KB each: x tile 16KB + wb tile 16KB
// phase 2 (overlaps): ysw 64KB @0 ; W1 32KB @64K ; W2 32KB @96K ; h 64KB @128K
#define BUF(i)  ((i) * 32768)
#define YSW_OFF 0
#define W1_OFF  65536
#define W2_OFF  98304
#define H_OFF   131072
#define SMEM_TOTAL 196608

__device__ __forceinline__ uint32_t f2tf(float f) {
    uint32_t u; asm("cvt.rna.tf32.f32 %0, %1;" : "=r"(u) : "f"(f)); return u;
}
__device__ __forceinline__ void cpa16(uint32_t dst, const void* src) {
    asm volatile("cp.async.cg.shared.global [%0], [%1], 16;"
                 :: "r"(dst), "l"(src) : "memory");
}
__device__ __forceinline__ void cp_commit() {
    asm volatile("cp.async.commit_group;" ::: "memory");
}
template <int N>
__device__ __forceinline__ void cp_wait() {
    asm volatile("cp.async.wait_group %0;" :: "n"(N) : "memory");
}
__device__ __forceinline__ void ldsm4(uint32_t& r0, uint32_t& r1, uint32_t& r2,
                                      uint32_t& r3, uint32_t addr) {
    asm volatile("ldmatrix.sync.aligned.m8n8.x4.shared.b16 {%0,%1,%2,%3}, [%4];"
                 : "=r"(r0), "=r"(r1), "=r"(r2), "=r"(r3) : "r"(addr));
}
__device__ __forceinline__ void mma8(float* c, const uint32_t* a, const uint32_t* b) {
    asm volatile("mma.sync.aligned.m16n8k8.row.col.f32.tf32.tf32.f32 "
                 "{%0,%1,%2,%3},{%4,%5,%6,%7},{%8,%9},{%0,%1,%2,%3};"
                 : "+f"(c[0]), "+f"(c[1]), "+f"(c[2]), "+f"(c[3])
                 : "r"(a[0]), "r"(a[1]), "r"(a[2]), "r"(a[3]),
                   "r"(b[0]), "r"(b[1]));
}

// ================= prep: convert inputs to tf32 / pre-swizzled images =================
__global__ void prep_kernel(const float* __restrict__ x,  const float* __restrict__ Wb,
                            const float* __restrict__ W1, const float* __restrict__ W2)
{
    const int tid = blockIdx.x * blockDim.x + threadIdx.x;
    const int nth = gridDim.x * blockDim.x;

    for (int i = tid; i < XN / 4; i += nth) {
        float4 v = ((const float4*)x)[i];
        ((uint4*)g_xt)[i] = make_uint4(f2tf(v.x), f2tf(v.y), f2tf(v.z), f2tf(v.w));
    }
    for (int i = tid; i < WBN / 4; i += nth) {
        float4 v = ((const float4*)Wb)[i];
        ((uint4*)g_wbt)[i] = make_uint4(f2tf(v.x), f2tf(v.y), f2tf(v.z), f2tf(v.w));
    }
    // W1 [s][c][h] -> image: u32 off = h*64 + (((c>>2)^(h&7))<<2) + (c&3)
    for (int i = tid; i < 64 * 64 * 128; i += nth) {
        int s = i >> 13, c = (i >> 7) & 63, h = i & 127;
        uint32_t off = h * 64 + ((((c >> 2) ^ (h & 7)) << 2) | (c & 3));
        g_w1img[s * 8192 + off] = f2tf(W1[i]);
    }
    // W2 [s][h][c] -> image: u32 off = c*128 + (((h>>2)^(c&7))<<2) + (h&3)
    for (int i = tid; i < 64 * 128 * 64; i += nth) {
        int s = i >> 13, h = (i >> 6) & 127, c = i & 63;
        uint32_t off = c * 128 + ((((h >> 2) ^ (c & 7)) << 2) | (h & 3));
        g_w2img[s * 8192 + off] = f2tf(W2[i]);
    }
}

// issue one k-tile (x[128x32] + wb[128x32]) into staging buffer b
__device__ __forceinline__ void issue_tile(uint32_t su, const uint32_t* xg,
                                           const uint32_t* wbg, int kt, int b, int tid)
{
    const int k0 = kt * 32;
    #pragma unroll
    for (int i = 0; i < 4; i++) {
        int idx = tid + i * NTH;
        int r = idx >> 3, c4 = idx & 7;
        cpa16(su + BUF(b) + r * 128 + ((c4 ^ (r & 7)) << 4),
              xg + (size_t)r * D_IN + k0 + c4 * 4);
    }
    #pragma unroll
    for (int i = 0; i < 4; i++) {
        int idx = tid + i * NTH;
        int n = idx >> 3, c4 = idx & 7;
        cpa16(su + BUF(b) + 16384 + n * 128 + ((c4 ^ (n & 7)) << 4),
              wbg + (size_t)n * D_IN + k0 + c4 * 4);
    }
}

__global__ __launch_bounds__(NTH, 1)
void kasmina_main_kernel(const float* __restrict__ bb,
                         const float* __restrict__ b1,
                         const float* __restrict__ b2,
                         const float* __restrict__ alpha,
                         const int*   __restrict__ active,
                         float* __restrict__ out)
{
    extern __shared__ char smem[];
    const uint32_t su = (uint32_t)__cvta_generic_to_shared(smem);

    const int bx   = blockIdx.x;          // 128 out cols: [bx*128, bx*128+128)
    const int row0 = blockIdx.y * 128;

    const int tid    = threadIdx.x;
    const int lane   = tid & 31;
    const int wid    = tid >> 5;
    const int warp_m = wid & 1;
    const int warp_n = wid >> 1;

    const uint32_t* xg  = g_xt  + (size_t)row0 * D_IN;
    const uint32_t* wbg = g_wbt + (size_t)(bx * 128) * D_IN;

    // ================= base GEMM: 4-stage cp.async pipeline =================
    float acc[4][4][4];
    #pragma unroll
    for (int mt = 0; mt < 4; mt++)
        #pragma unroll
        for (int nt = 0; nt < 4; nt++)
            #pragma unroll
            for (int q = 0; q < 4; q++) acc[mt][nt][q] = 0.f;

    issue_tile(su, xg, wbg, 0, 0, tid); cp_commit();
    issue_tile(su, xg, wbg, 1, 1, tid); cp_commit();

    #pragma unroll 1
    for (int ks = 0; ks < 32; ks++) {
        if (ks + 2 < 32) issue_tile(su, xg, wbg, ks + 2, (ks + 2) & 3, tid);
        cp_commit();
        cp_wait<2>();
        __syncthreads();

        const uint32_t xs  = su + BUF(ks & 3);
        const uint32_t wbs = xs + 16384;
        #pragma unroll
        for (int kk = 0; kk < 4; kk++) {
            uint32_t a[4][4], b[4][2];
            #pragma unroll
            for (int mt = 0; mt < 4; mt++) {
                int row = warp_m * 64 + mt * 16 + ((lane >> 3) & 1) * 8 + (lane & 7);
                int hi  = lane >> 4;
                uint32_t ad = xs + row * 128 + ((((kk << 1) | hi) ^ (row & 7)) << 4);
                ldsm4(a[mt][0], a[mt][1], a[mt][2], a[mt][3], ad);
            }
            #pragma unroll
            for (int p = 0; p < 2; p++) {
                int row = warp_n * 32 + p * 16 + (lane >> 4) * 8 + (lane & 7);
                int hi  = (lane >> 3) & 1;
                uint32_t ad = wbs + row * 128 + ((((kk << 1) | hi) ^ (row & 7)) << 4);
                ldsm4(b[2*p][0], b[2*p][1], b[2*p+1][0], b[2*p+1][1], ad);
            }
            #pragma unroll
            for (int mt = 0; mt < 4; mt++)
                #pragma unroll
                for (int nt = 0; nt < 4; nt++)
                    mma8(acc[mt][nt], a[mt], b[nt]);
        }
    }

    // ---- epilogue: y = acc + bb -> swizzled fp32 smem (ysw) ----
    // layout: addr = r*512 + (((c>>2)^(r&7))<<4) + (c&3)*4, r,c in [0,128)
    #pragma unroll
    for (int mt = 0; mt < 4; mt++) {
        #pragma unroll
        for (int nt = 0; nt < 4; nt++) {
            int c0 = warp_n * 32 + nt * 8 + 2 * (lane & 3);
            float2 bbv = *(const float2*)&bb[bx * 128 + c0];
            int r0 = warp_m * 64 + mt * 16 + (lane >> 2);
            uint32_t swz = (((c0 >> 2) ^ (r0 & 7)) << 4) + (c0 & 3) * 4;
            *(float2*)(smem + YSW_OFF + r0 * 512 + swz) =
                make_float2(acc[mt][nt][0] + bbv.x, acc[mt][nt][1] + bbv.y);
            swz = (((c0 >> 2) ^ ((r0 + 8) & 7)) << 4) + (c0 & 3) * 4;
            *(float2*)(smem + YSW_OFF + (r0 + 8) * 512 + swz) =
                make_float2(acc[mt][nt][2] + bbv.x, acc[mt][nt][3] + bbv.y);
        }
    }
    __syncthreads();

    const uint32_t ysw_b = su + YSW_OFF;
    const uint32_t w1_b  = su + W1_OFF;
    const uint32_t w2_b  = su + W2_OFF;
    const uint32_t h_b   = su + H_OFF;

    // ================= per-seed MLP + blend (2 seeds) =================
    #pragma unroll 1
    for (int sl = 0; sl < 2; sl++) {
        const int sg = bx * 2 + sl;

        // bulk cp.async of pre-swizzled W1/W2 images (32KB each)
        {
            const uint32_t* w1src = g_w1img + (size_t)sg * 8192;
            const uint32_t* w2src = g_w2img + (size_t)sg * 8192;
            #pragma unroll
            for (int i = 0; i < 8; i++) {
                int c = tid + i * NTH;             // 0..2047 chunks
                cpa16(su + W1_OFF + c * 16, w1src + c * 4);
                cpa16(su + W2_OFF + c * 16, w2src + c * 4);
            }
            cp_commit();
            cp_wait<0>();
        }
        __syncthreads();

        // ---- stage A: h = relu(y @ W1 + b1)   M=128 N=128 K=64 ----
        {
            float accA[4][4][4];
            #pragma unroll
            for (int mt = 0; mt < 4; mt++)
                #pragma unroll
                for (int nt = 0; nt < 4; nt++)
                    #pragma unroll
                    for (int q = 0; q < 4; q++) accA[mt][nt][q] = 0.f;

            #pragma unroll 2
            for (int kk = 0; kk < 8; kk++) {
                uint32_t a[4][4], b[4][2];
                #pragma unroll
                for (int mt = 0; mt < 4; mt++) {
                    int row = warp_m * 64 + mt * 16 + ((lane >> 3) & 1) * 8 + (lane & 7);
                    int hi  = lane >> 4;
                    uint32_t ad = ysw_b + row * 512 +
                        (((sl * 16 + ((kk << 1) | hi)) ^ (row & 7)) << 4);
                    ldsm4(a[mt][0], a[mt][1], a[mt][2], a[mt][3], ad);
                    #pragma unroll
                    for (int q = 0; q < 4; q++)
                        a[mt][q] = f2tf(__uint_as_float(a[mt][q]));
                }
                #pragma unroll
                for (int p = 0; p < 2; p++) {
                    int row = warp_n * 32 + p * 16 + (lane >> 4) * 8 + (lane & 7);
                    int hi  = (lane >> 3) & 1;
                    uint32_t ad = w1_b + row * 256 + ((((kk << 1) | hi) ^ (row & 7)) << 4);
                    ldsm4(b[2*p][0], b[2*p][1], b[2*p+1][0], b[2*p+1][1], ad);
                }
                #pragma unroll
                for (int mt = 0; mt < 4; mt++)
                    #pragma unroll
                    for (int nt = 0; nt < 4; nt++)
                        mma8(accA[mt][nt], a[mt], b[nt]);
            }

            // bias + relu + cvt -> h (tf32 swizzled, stride 512)
            #pragma unroll
            for (int mt = 0; mt < 4; mt++) {
                #pragma unroll
                for (int nt = 0; nt < 4; nt++) {
                    int h0 = warp_n * 32 + nt * 8 + 2 * (lane & 3);
                    float2 b1v = *(const float2*)&b1[sg * 128 + h0];
                    int r0 = warp_m * 64 + mt * 16 + (lane >> 2);
                    float v0 = fmaxf(accA[mt][nt][0] + b1v.x, 0.f);
                    float v1 = fmaxf(accA[mt][nt][1] + b1v.y, 0.f);
                    float v2 = fmaxf(accA[mt][nt][2] + b1v.x, 0.f);
                    float v3 = fmaxf(accA[mt][nt][3] + b1v.y, 0.f);
                    uint32_t swz = (((h0 >> 2) ^ (r0 & 7)) << 4) + (h0 & 3) * 4;
                    *(uint2*)(smem + H_OFF + r0 * 512 + swz) =
                        make_uint2(f2tf(v0), f2tf(v1));
                    *(uint2*)(smem + H_OFF + (r0 + 8) * 512 + swz) =
                        make_uint2(f2tf(v2), f2tf(v3));
                }
            }
        }
        __syncthreads();

        // ---- stage B: bp = h @ W2 + b2; blend; store   M=128 N=64 K=128 ----
        {
            float accB[4][2][4];
            #pragma unroll
            for (int mt = 0; mt < 4; mt++)
                #pragma unroll
                for (int nt = 0; nt < 2; nt++)
                    #pragma unroll
                    for (int q = 0; q < 4; q++) accB[mt][nt][q] = 0.f;

            #pragma unroll 4
            for (int kk = 0; kk < 16; kk++) {
                uint32_t a[4][4], b[2][2];
                #pragma unroll
                for (int mt = 0; mt < 4; mt++) {
                    int row = warp_m * 64 + mt * 16 + ((lane >> 3) & 1) * 8 + (lane & 7);
                    int hi  = lane >> 4;
                    uint32_t ad = h_b + row * 512 + ((((kk << 1) | hi) ^ (row & 7)) << 4);
                    ldsm4(a[mt][0], a[mt][1], a[mt][2], a[mt][3], ad);
                }
                {
                    int row = warp_n * 16 + (lane >> 4) * 8 + (lane & 7);
                    int hi  = (lane >> 3) & 1;
                    uint32_t ad = w2_b + row * 512 + ((((kk << 1) | hi) ^ (row & 7)) << 4);
                    ldsm4(b[0][0], b[0][1], b[1][0], b[1][1], ad);
                }
                #pragma unroll
                for (int mt = 0; mt < 4; mt++)
                    #pragma unroll
                    for (int nt = 0; nt < 2; nt++)
                        mma8(accB[mt][nt], a[mt], b[nt]);
            }

            const float aw  = alpha[sg] * (active[sg] != 0 ? 1.f : 0.f);
            const float omw = 1.f - aw;
            #pragma unroll
            for (int mt = 0; mt < 4; mt++) {
                #pragma unroll
                for (int nt = 0; nt < 2; nt++) {
                    int c0 = warp_n * 16 + nt * 8 + 2 * (lane & 3);
                    float2 b2v = *(const float2*)&b2[sg * 64 + c0];
                    int r0 = warp_m * 64 + mt * 16 + (lane >> 2);
                    int cy = sl * 64 + c0;

                    float2 y0 = *(const float2*)(smem + YSW_OFF + r0 * 512 +
                                  (((cy >> 2) ^ (r0 & 7)) << 4) + (cy & 3) * 4);
                    float o0 = omw * y0.x + aw * (accB[mt][nt][0] + b2v.x);
                    float o1 = omw * y0.y + aw * (accB[mt][nt][1] + b2v.y);
                    *(float2*)&out[(size_t)(row0 + r0) * D_OUT + bx * 128 + cy] =
                        make_float2(o0, o1);

                    float2 y1 = *(const float2*)(smem + YSW_OFF + (r0 + 8) * 512 +
                                  (((cy >> 2) ^ ((r0 + 8) & 7)) << 4) + (cy & 3) * 4);
                    float o2 = omw * y1.x + aw * (accB[mt][nt][2] + b2v.x);
                    float o3 = omw * y1.y + aw * (accB[mt][nt][3] + b2v.y);
                    *(float2*)&out[(size_t)(row0 + r0 + 8) * D_OUT + bx * 128 + cy] =
                        make_float2(o2, o3);
                }
            }
        }
        __syncthreads();
    }
}

extern "C" void kernel_launch(void* const* d_in, const int* in_sizes, int n_in,
                              void* d_out, int out_size)
{
    const float* x      = (const float*)d_in[0];
    const float* Wb     = (const float*)d_in[1];
    const float* bb     = (const float*)d_in[2];
    const float* W1     = (const float*)d_in[3];
    const float* b1     = (const float*)d_in[4];
    const float* W2     = (const float*)d_in[5];
    const float* b2     = (const float*)d_in[6];
    const float* alpha  = (const float*)d_in[7];
    const int*   active = (const int*)d_in[8];
    float* out = (float*)d_out;

    prep_kernel<<<1024, 256>>>(x, Wb, W1, W2);

    cudaFuncSetAttribute(kasmina_main_kernel,
                         cudaFuncAttributeMaxDynamicSharedMemorySize, SMEM_TOTAL);
    dim3 grid(32, 64);
    kasmina_main_kernel<<<grid, NTH, SMEM_TOTAL>>>(
        bb, b1, b2, alpha, active, out);
}

// round 6
// speedup vs baseline: 7.7721x; 1.7647x over previous
#include <cuda_runtime.h>
#include <cuda_fp16.h>
#include <cstdint>

#define NTH    256
#define D_IN   1024
#define D_OUT  4096
#define XN     (8192 * 1024)
#define WBN    (4096 * 1024)

__device__ __half g_xh[XN];           // x  as fp16
__device__ __half g_wbh[WBN];         // Wb as fp16
__device__ __half g_w1img[64 * 8192]; // W1 pre-swizzled smem images (16KB/seed)
__device__ __half g_w2img[64 * 8192]; // W2 pre-swizzled smem images

// ---------------- smem layout (bytes) ----------------
// phase 1: 4 staging buffers 32KB each (x tile 16KB + wb tile 16KB), k-tile=64
// phase 2 (reuses 0..131071 only for yf/ysw/h; W images live above staging):
//   yf  fp32 [128][132]     0      .. 67583   (67584)
//   ysw fp16 [128][128] swz 67584  .. 100351  (32768)
//   h   fp16 [128][128] swz 100352 .. 133119  (32768)
//   W images dbl buffered   133120 .. 198655  (2 x 32768)
//   bbs fp32 [128]          198656 .. 199167
#define BUF(i)   ((i) * 32768)
#define YF_OFF   0
#define YF_STR   132
#define YSW_OFF  67584
#define H_OFF    100352
#define W_OFF(p) (133120 + (p) * 32768)   // W1 at +0, W2 at +16384
#define BBS_OFF  198656
#define SMEM_TOTAL 199168

__device__ __forceinline__ uint32_t h2u(__half2 h) {
    return *reinterpret_cast<uint32_t*>(&h);
}
__device__ __forceinline__ void cpa16(uint32_t dst, const void* src) {
    asm volatile("cp.async.cg.shared.global [%0], [%1], 16;"
                 :: "r"(dst), "l"(src) : "memory");
}
__device__ __forceinline__ void cp_commit() {
    asm volatile("cp.async.commit_group;" ::: "memory");
}
template <int N>
__device__ __forceinline__ void cp_wait() {
    asm volatile("cp.async.wait_group %0;" :: "n"(N) : "memory");
}
__device__ __forceinline__ void ldsm4(uint32_t& r0, uint32_t& r1, uint32_t& r2,
                                      uint32_t& r3, uint32_t addr) {
    asm volatile("ldmatrix.sync.aligned.m8n8.x4.shared.b16 {%0,%1,%2,%3}, [%4];"
                 : "=r"(r0), "=r"(r1), "=r"(r2), "=r"(r3) : "r"(addr));
}
__device__ __forceinline__ void mma16(float* c, const uint32_t* a, const uint32_t* b) {
    asm volatile("mma.sync.aligned.m16n8k16.row.col.f32.f16.f16.f32 "
                 "{%0,%1,%2,%3},{%4,%5,%6,%7},{%8,%9},{%0,%1,%2,%3};"
                 : "+f"(c[0]), "+f"(c[1]), "+f"(c[2]), "+f"(c[3])
                 : "r"(a[0]), "r"(a[1]), "r"(a[2]), "r"(a[3]),
                   "r"(b[0]), "r"(b[1]));
}

// ============== prep: fp16 conversions + pre-swizzled W images ==============
__global__ void prep_kernel(const float* __restrict__ x,  const float* __restrict__ Wb,
                            const float* __restrict__ W1, const float* __restrict__ W2)
{
    const int tid = blockIdx.x * blockDim.x + threadIdx.x;
    const int nth = gridDim.x * blockDim.x;

    for (int i = tid; i < XN / 4; i += nth) {
        float4 v = ((const float4*)x)[i];
        uint2 u = make_uint2(h2u(__floats2half2_rn(v.x, v.y)),
                             h2u(__floats2half2_rn(v.z, v.w)));
        ((uint2*)g_xh)[i] = u;
    }
    for (int i = tid; i < WBN / 4; i += nth) {
        float4 v = ((const float4*)Wb)[i];
        uint2 u = make_uint2(h2u(__floats2half2_rn(v.x, v.y)),
                             h2u(__floats2half2_rn(v.z, v.w)));
        ((uint2*)g_wbh)[i] = u;
    }
    // W1 [s][c][h] -> image [h][c], row=64 fp16=128B, swizzled
    for (int i = tid; i < 64 * 64 * 128; i += nth) {
        int s = i >> 13, c = (i >> 7) & 63, h = i & 127;
        int off = h * 64 + ((((c >> 3) ^ (h & 7)) << 3) | (c & 7));
        g_w1img[s * 8192 + off] = __float2half(W1[i]);
    }
    // W2 [s][h][c] -> image [c][h], row=128 fp16=256B, swizzled
    for (int i = tid; i < 64 * 128 * 64; i += nth) {
        int s = i >> 13, h = (i >> 6) & 127, c = i & 63;
        int off = c * 128 + ((((h >> 3) ^ (c & 7)) << 3) | (h & 7));
        g_w2img[s * 8192 + off] = __float2half(W2[i]);
    }
}

// stage one k-tile (k=64): x[128x64]h + wb[128x64]h, both 16KB, 128B rows
__device__ __forceinline__ void issue_tile(uint32_t su, const __half* xg,
                                           const __half* wbg, int kt, int b, int tid)
{
    const int k0 = kt * 64;
    #pragma unroll
    for (int i = 0; i < 4; i++) {
        int idx = tid + i * NTH;
        int r = idx >> 3, c4 = idx & 7;
        cpa16(su + BUF(b) + r * 128 + ((c4 ^ (r & 7)) << 4),
              xg + (size_t)r * D_IN + k0 + c4 * 8);
    }
    #pragma unroll
    for (int i = 0; i < 4; i++) {
        int idx = tid + i * NTH;
        int n = idx >> 3, c4 = idx & 7;
        cpa16(su + BUF(b) + 16384 + n * 128 + ((c4 ^ (n & 7)) << 4),
              wbg + (size_t)n * D_IN + k0 + c4 * 8);
    }
}

__global__ __launch_bounds__(NTH, 1)
void kasmina_main_kernel(const float* __restrict__ bb,
                         const float* __restrict__ b1,
                         const float* __restrict__ b2,
                         const float* __restrict__ alpha,
                         const int*   __restrict__ active,
                         float* __restrict__ out)
{
    extern __shared__ char smem[];
    const uint32_t su = (uint32_t)__cvta_generic_to_shared(smem);
    float* yf  = (float*)(smem + YF_OFF);
    float* bbs = (float*)(smem + BBS_OFF);

    const int bx   = blockIdx.x;          // out cols [bx*128, bx*128+128)
    const int row0 = blockIdx.y * 128;

    const int tid    = threadIdx.x;
    const int lane   = tid & 31;
    const int wid    = tid >> 5;
    const int warp_m = wid & 1;
    const int warp_n = wid >> 1;

    const __half* xg  = g_xh  + (size_t)row0 * D_IN;
    const __half* wbg = g_wbh + (size_t)(bx * 128) * D_IN;

    if (tid < 128) bbs[tid] = bb[bx * 128 + tid];

    // ================= base GEMM: fp16 mma, 16 k-tiles, depth-3 pipeline =================
    float acc[4][4][4];
    #pragma unroll
    for (int mt = 0; mt < 4; mt++)
        #pragma unroll
        for (int nt = 0; nt < 4; nt++)
            #pragma unroll
            for (int q = 0; q < 4; q++) acc[mt][nt][q] = 0.f;

    issue_tile(su, xg, wbg, 0, 0, tid); cp_commit();
    issue_tile(su, xg, wbg, 1, 1, tid); cp_commit();

    #pragma unroll 1
    for (int ks = 0; ks < 16; ks++) {
        if (ks + 2 < 16) issue_tile(su, xg, wbg, ks + 2, (ks + 2) & 3, tid);
        cp_commit();
        cp_wait<2>();
        __syncthreads();

        const uint32_t xs  = su + BUF(ks & 3);
        const uint32_t wbs = xs + 16384;
        #pragma unroll
        for (int kk = 0; kk < 4; kk++) {
            uint32_t a[4][4], b[4][2];
            #pragma unroll
            for (int mt = 0; mt < 4; mt++) {
                int row = warp_m * 64 + mt * 16 + ((lane >> 3) & 1) * 8 + (lane & 7);
                int ch  = kk * 2 + (lane >> 4);
                ldsm4(a[mt][0], a[mt][1], a[mt][2], a[mt][3],
                      xs + row * 128 + ((ch ^ (row & 7)) << 4));
            }
            #pragma unroll
            for (int p = 0; p < 2; p++) {
                int row = warp_n * 32 + p * 16 + (lane >> 4) * 8 + (lane & 7);
                int ch  = kk * 2 + ((lane >> 3) & 1);
                ldsm4(b[2*p][0], b[2*p][1], b[2*p+1][0], b[2*p+1][1],
                      wbs + row * 128 + ((ch ^ (row & 7)) << 4));
            }
            #pragma unroll
            for (int mt = 0; mt < 4; mt++)
                #pragma unroll
                for (int nt = 0; nt < 4; nt++)
                    mma16(acc[mt][nt], a[mt], b[nt]);
        }
    }
    cp_wait<0>();
    __syncthreads();   // all staging reads done before yf/ysw writes reuse the space

    // prefetch seed-0 W images (region disjoint from staging; overlaps epilogue)
    {
        const __half* w1s = g_w1img + (size_t)(bx * 2) * 8192;
        const __half* w2s = g_w2img + (size_t)(bx * 2) * 8192;
        #pragma unroll
        for (int i = 0; i < 4; i++) {
            int c = tid + i * NTH;
            cpa16(su + W_OFF(0) + c * 16, w1s + c * 8);
            cpa16(su + W_OFF(0) + 16384 + c * 16, w2s + c * 8);
        }
        cp_commit();
    }

    // epilogue: y = acc + bb -> yf (fp32, stride 132) and ysw (fp16 swizzled)
    #pragma unroll
    for (int mt = 0; mt < 4; mt++) {
        #pragma unroll
        for (int nt = 0; nt < 4; nt++) {
            int c0 = warp_n * 32 + nt * 8 + 2 * (lane & 3);
            int r0 = warp_m * 64 + mt * 16 + (lane >> 2);
            float bx0 = bbs[c0], bx1 = bbs[c0 + 1];
            float v00 = acc[mt][nt][0] + bx0, v01 = acc[mt][nt][1] + bx1;
            float v10 = acc[mt][nt][2] + bx0, v11 = acc[mt][nt][3] + bx1;
            *(float2*)&yf[r0 * YF_STR + c0]       = make_float2(v00, v01);
            *(float2*)&yf[(r0 + 8) * YF_STR + c0] = make_float2(v10, v11);
            uint32_t sw0 = (((c0 >> 3) ^ (r0 & 7)) << 4) + ((c0 * 2) & 15);
            uint32_t sw1 = (((c0 >> 3) ^ ((r0 + 8) & 7)) << 4) + ((c0 * 2) & 15);
            *(uint32_t*)(smem + YSW_OFF + r0 * 256 + sw0) =
                h2u(__floats2half2_rn(v00, v01));
            *(uint32_t*)(smem + YSW_OFF + (r0 + 8) * 256 + sw1) =
                h2u(__floats2half2_rn(v10, v11));
        }
    }
    cp_wait<0>();
    __syncthreads();   // W0 + ysw + yf visible

    // prefetch seed-1 W images
    {
        const __half* w1s = g_w1img + (size_t)(bx * 2 + 1) * 8192;
        const __half* w2s = g_w2img + (size_t)(bx * 2 + 1) * 8192;
        #pragma unroll
        for (int i = 0; i < 4; i++) {
            int c = tid + i * NTH;
            cpa16(su + W_OFF(1) + c * 16, w1s + c * 8);
            cpa16(su + W_OFF(1) + 16384 + c * 16, w2s + c * 8);
        }
        cp_commit();
    }

    const uint32_t ysw_b = su + YSW_OFF;
    const uint32_t h_b   = su + H_OFF;

    // ================= per-seed MLP + blend =================
    #pragma unroll 1
    for (int sl = 0; sl < 2; sl++) {
        const int sg = bx * 2 + sl;
        const uint32_t w1b = su + W_OFF(sl);
        const uint32_t w2b = w1b + 16384;

        if (sl) { cp_wait<0>(); __syncthreads(); }

        // ---- stage A: h = relu(y @ W1 + b1)   M=128 N=128 K=64 ----
        {
            float accA[4][4][4];
            #pragma unroll
            for (int mt = 0; mt < 4; mt++)
                #pragma unroll
                for (int nt = 0; nt < 4; nt++)
                    #pragma unroll
                    for (int q = 0; q < 4; q++) accA[mt][nt][q] = 0.f;

            #pragma unroll
            for (int kk = 0; kk < 4; kk++) {
                uint32_t a[4][4], b[4][2];
                #pragma unroll
                for (int mt = 0; mt < 4; mt++) {
                    int row = warp_m * 64 + mt * 16 + ((lane >> 3) & 1) * 8 + (lane & 7);
                    int ch  = sl * 8 + kk * 2 + (lane >> 4);
                    ldsm4(a[mt][0], a[mt][1], a[mt][2], a[mt][3],
                          ysw_b + row * 256 + ((ch ^ (row & 7)) << 4));
                }
                #pragma unroll
                for (int p = 0; p < 2; p++) {
                    int row = warp_n * 32 + p * 16 + (lane >> 4) * 8 + (lane & 7);
                    int ch  = kk * 2 + ((lane >> 3) & 1);
                    ldsm4(b[2*p][0], b[2*p][1], b[2*p+1][0], b[2*p+1][1],
                          w1b + row * 128 + ((ch ^ (row & 7)) << 4));
                }
                #pragma unroll
                for (int mt = 0; mt < 4; mt++)
                    #pragma unroll
                    for (int nt = 0; nt < 4; nt++)
                        mma16(accA[mt][nt], a[mt], b[nt]);
            }

            // bias + relu -> h (fp16 swizzled)
            #pragma unroll
            for (int mt = 0; mt < 4; mt++) {
                #pragma unroll
                for (int nt = 0; nt < 4; nt++) {
                    int h0 = warp_n * 32 + nt * 8 + 2 * (lane & 3);
                    int r0 = warp_m * 64 + mt * 16 + (lane >> 2);
                    float2 b1v = *(const float2*)&b1[sg * 128 + h0];
                    float v0 = fmaxf(accA[mt][nt][0] + b1v.x, 0.f);
                    float v1 = fmaxf(accA[mt][nt][1] + b1v.y, 0.f);
                    float v2 = fmaxf(accA[mt][nt][2] + b1v.x, 0.f);
                    float v3 = fmaxf(accA[mt][nt][3] + b1v.y, 0.f);
                    uint32_t sw0 = (((h0 >> 3) ^ (r0 & 7)) << 4) + ((h0 * 2) & 15);
                    uint32_t sw1 = (((h0 >> 3) ^ ((r0 + 8) & 7)) << 4) + ((h0 * 2) & 15);
                    *(uint32_t*)(smem + H_OFF + r0 * 256 + sw0) =
                        h2u(__floats2half2_rn(v0, v1));
                    *(uint32_t*)(smem + H_OFF + (r0 + 8) * 256 + sw1) =
                        h2u(__floats2half2_rn(v2, v3));
                }
            }
        }
        __syncthreads();

        // ---- stage B: bp = h @ W2 + b2; blend; store   M=128 N=64 K=128 ----
        {
            float accB[4][2][4];
            #pragma unroll
            for (int mt = 0; mt < 4; mt++)
                #pragma unroll
                for (int nt = 0; nt < 2; nt++)
                    #pragma unroll
                    for (int q = 0; q < 4; q++) accB[mt][nt][q] = 0.f;

            #pragma unroll 2
            for (int kk = 0; kk < 8; kk++) {
                uint32_t a[4][4], b[2][2];
                #pragma unroll
                for (int mt = 0; mt < 4; mt++) {
                    int row = warp_m * 64 + mt * 16 + ((lane >> 3) & 1) * 8 + (lane & 7);
                    int ch  = kk * 2 + (lane >> 4);
                    ldsm4(a[mt][0], a[mt][1], a[mt][2], a[mt][3],
                          h_b + row * 256 + ((ch ^ (row & 7)) << 4));
                }
                {
                    int row = warp_n * 16 + (lane >> 4) * 8 + (lane & 7);
                    int ch  = kk * 2 + ((lane >> 3) & 1);
                    ldsm4(b[0][0], b[0][1], b[1][0], b[1][1],
                          w2b + row * 256 + ((ch ^ (row & 7)) << 4));
                }
                #pragma unroll
                for (int mt = 0; mt < 4; mt++)
                    #pragma unroll
                    for (int nt = 0; nt < 2; nt++)
                        mma16(accB[mt][nt], a[mt], b[nt]);
            }

            const float aw  = alpha[sg] * (active[sg] != 0 ? 1.f : 0.f);
            const float omw = 1.f - aw;
            #pragma unroll
            for (int mt = 0; mt < 4; mt++) {
                #pragma unroll
                for (int nt = 0; nt < 2; nt++) {
                    int c0 = warp_n * 16 + nt * 8 + 2 * (lane & 3);
                    int cy = sl * 64 + c0;
                    int r0 = warp_m * 64 + mt * 16 + (lane >> 2);
                    float2 b2v = *(const float2*)&b2[sg * 64 + c0];

                    float2 y0 = *(const float2*)&yf[r0 * YF_STR + cy];
                    *(float2*)&out[(size_t)(row0 + r0) * D_OUT + bx * 128 + cy] =
                        make_float2(omw * y0.x + aw * (accB[mt][nt][0] + b2v.x),
                                    omw * y0.y + aw * (accB[mt][nt][1] + b2v.y));

                    float2 y1 = *(const float2*)&yf[(r0 + 8) * YF_STR + cy];
                    *(float2*)&out[(size_t)(row0 + r0 + 8) * D_OUT + bx * 128 + cy] =
                        make_float2(omw * y1.x + aw * (accB[mt][nt][2] + b2v.x),
                                    omw * y1.y + aw * (accB[mt][nt][3] + b2v.y));
                }
            }
        }
        __syncthreads();
    }
}

extern "C" void kernel_launch(void* const* d_in, const int* in_sizes, int n_in,
                              void* d_out, int out_size)
{
    const float* x      = (const float*)d_in[0];
    const float* Wb     = (const float*)d_in[1];
    const float* bb     = (const float*)d_in[2];
    const float* W1     = (const float*)d_in[3];
    const float* b1     = (const float*)d_in[4];
    const float* W2     = (const float*)d_in[5];
    const float* b2     = (const float*)d_in[6];
    const float* alpha  = (const float*)d_in[7];
    const int*   active = (const int*)d_in[8];
    float* out = (float*)d_out;

    prep_kernel<<<1024, 256>>>(x, Wb, W1, W2);

    cudaFuncSetAttribute(kasmina_main_kernel,
                         cudaFuncAttributeMaxDynamicSharedMemorySize, SMEM_TOTAL);
    dim3 grid(32, 64);
    kasmina_main_kernel<<<grid, NTH, SMEM_TOTAL>>>(
        bb, b1, b2, alpha, active, out);
}

// round 7
// speedup vs baseline: 9.2366x; 1.1884x over previous
#include <cuda_runtime.h>
#include <cuda_fp16.h>
#include <cstdint>

#define NTH    256
#define D_IN   1024
#define D_OUT  4096
#define XN     (8192 * 1024)
#define WBN    (4096 * 1024)

__device__ __half g_xh[XN];           // x  as fp16
__device__ __half g_wbh[WBN];         // Wb as fp16
__device__ __half g_w1img[64 * 8192]; // W1 pre-swizzled smem images (16KB/seed)
__device__ __half g_w2img[64 * 8192]; // W2 pre-swizzled smem images

// ---------------- smem layout (bytes) ----------------
// phase 1: 2 staging buffers 32KB (x 16KB + wb 16KB each), k-tile=64
// phase 2 reuses staging region:
//   ysw fp16 [128][128] swz   0     .. 32767
//   h   fp16 [128][128] swz   32768 .. 65535
//   W   (W1 16KB + W2 16KB)   65536 .. 98303   (own region, never staged over)
//   bbs fp32 [128]            98304 .. 98815
#define BUF(i)   ((i) * 32768)
#define YSW_OFF  0
#define H_OFF    32768
#define W_OFF    65536
#define BBS_OFF  98304
#define SMEM_TOTAL 98816

__device__ __forceinline__ uint32_t h2u(__half2 h) {
    return *reinterpret_cast<uint32_t*>(&h);
}
__device__ __forceinline__ void cpa16(uint32_t dst, const void* src) {
    asm volatile("cp.async.cg.shared.global [%0], [%1], 16;"
                 :: "r"(dst), "l"(src) : "memory");
}
__device__ __forceinline__ void cp_commit() {
    asm volatile("cp.async.commit_group;" ::: "memory");
}
template <int N>
__device__ __forceinline__ void cp_wait() {
    asm volatile("cp.async.wait_group %0;" :: "n"(N) : "memory");
}
__device__ __forceinline__ void ldsm4(uint32_t& r0, uint32_t& r1, uint32_t& r2,
                                      uint32_t& r3, uint32_t addr) {
    asm volatile("ldmatrix.sync.aligned.m8n8.x4.shared.b16 {%0,%1,%2,%3}, [%4];"
                 : "=r"(r0), "=r"(r1), "=r"(r2), "=r"(r3) : "r"(addr));
}
__device__ __forceinline__ void mma16(float* c, const uint32_t* a, const uint32_t* b) {
    asm volatile("mma.sync.aligned.m16n8k16.row.col.f32.f16.f16.f32 "
                 "{%0,%1,%2,%3},{%4,%5,%6,%7},{%8,%9},{%0,%1,%2,%3};"
                 : "+f"(c[0]), "+f"(c[1]), "+f"(c[2]), "+f"(c[3])
                 : "r"(a[0]), "r"(a[1]), "r"(a[2]), "r"(a[3]),
                   "r"(b[0]), "r"(b[1]));
}

// ============== prep: fp16 conversions + pre-swizzled W images ==============
__global__ void prep_kernel(const float* __restrict__ x,  const float* __restrict__ Wb,
                            const float* __restrict__ W1, const float* __restrict__ W2)
{
    const int tid = blockIdx.x * blockDim.x + threadIdx.x;
    const int nth = gridDim.x * blockDim.x;

    for (int i = tid; i < XN / 4; i += nth) {
        float4 v = ((const float4*)x)[i];
        ((uint2*)g_xh)[i] = make_uint2(h2u(__floats2half2_rn(v.x, v.y)),
                                       h2u(__floats2half2_rn(v.z, v.w)));
    }
    for (int i = tid; i < WBN / 4; i += nth) {
        float4 v = ((const float4*)Wb)[i];
        ((uint2*)g_wbh)[i] = make_uint2(h2u(__floats2half2_rn(v.x, v.y)),
                                        h2u(__floats2half2_rn(v.z, v.w)));
    }
    // W1 [s][c][h] -> image [h][c], row=64 fp16=128B, swizzled
    for (int i = tid; i < 64 * 64 * 128; i += nth) {
        int s = i >> 13, c = (i >> 7) & 63, h = i & 127;
        int off = h * 64 + ((((c >> 3) ^ (h & 7)) << 3) | (c & 7));
        g_w1img[s * 8192 + off] = __float2half(W1[i]);
    }
    // W2 [s][h][c] -> image [c][h], row=128 fp16=256B, swizzled
    for (int i = tid; i < 64 * 128 * 64; i += nth) {
        int s = i >> 13, h = (i >> 6) & 127, c = i & 63;
        int off = c * 128 + ((((h >> 3) ^ (c & 7)) << 3) | (h & 7));
        g_w2img[s * 8192 + off] = __float2half(W2[i]);
    }
}

// stage one k-tile (k=64): x[128x64]h + wb[128x64]h, both 16KB, 128B rows
__device__ __forceinline__ void issue_tile(uint32_t su, const __half* xg,
                                           const __half* wbg, int kt, int b, int tid)
{
    const int k0 = kt * 64;
    #pragma unroll
    for (int i = 0; i < 4; i++) {
        int idx = tid + i * NTH;
        int r = idx >> 3, c4 = idx & 7;
        cpa16(su + BUF(b) + r * 128 + ((c4 ^ (r & 7)) << 4),
              xg + (size_t)r * D_IN + k0 + c4 * 8);
    }
    #pragma unroll
    for (int i = 0; i < 4; i++) {
        int idx = tid + i * NTH;
        int n = idx >> 3, c4 = idx & 7;
        cpa16(su + BUF(b) + 16384 + n * 128 + ((c4 ^ (n & 7)) << 4),
              wbg + (size_t)n * D_IN + k0 + c4 * 8);
    }
}

// load per-seed W images (W1 16KB + W2 16KB) via cp.async
__device__ __forceinline__ void issue_w(uint32_t su, int sg, int tid) {
    const __half* w1s = g_w1img + (size_t)sg * 8192;
    const __half* w2s = g_w2img + (size_t)sg * 8192;
    #pragma unroll
    for (int i = 0; i < 4; i++) {
        int c = tid + i * NTH;
        cpa16(su + W_OFF + c * 16, w1s + c * 8);
        cpa16(su + W_OFF + 16384 + c * 16, w2s + c * 8);
    }
}

__global__ __launch_bounds__(NTH, 2)
void kasmina_main_kernel(const float* __restrict__ bb,
                         const float* __restrict__ b1,
                         const float* __restrict__ b2,
                         const float* __restrict__ alpha,
                         const int*   __restrict__ active,
                         float* __restrict__ out)
{
    extern __shared__ char smem[];
    const uint32_t su = (uint32_t)__cvta_generic_to_shared(smem);
    float* bbs = (float*)(smem + BBS_OFF);

    const int bx   = blockIdx.x;          // out cols [bx*128, bx*128+128)
    const int row0 = blockIdx.y * 128;

    const int tid    = threadIdx.x;
    const int lane   = tid & 31;
    const int wid    = tid >> 5;
    const int warp_m = wid & 1;
    const int warp_n = wid >> 1;

    const __half* xg  = g_xh  + (size_t)row0 * D_IN;
    const __half* wbg = g_wbh + (size_t)(bx * 128) * D_IN;

    if (tid < 128) bbs[tid] = bb[bx * 128 + tid];

    // prefetch seed-0 W images (region disjoint from staging) + first tile
    issue_w(su, bx * 2, tid);               cp_commit();
    issue_tile(su, xg, wbg, 0, 0, tid);     cp_commit();

    // ================= base GEMM: fp16 mma, 16 k-tiles, double-buffered =================
    float acc[4][4][4];
    #pragma unroll
    for (int mt = 0; mt < 4; mt++)
        #pragma unroll
        for (int nt = 0; nt < 4; nt++)
            #pragma unroll
            for (int q = 0; q < 4; q++) acc[mt][nt][q] = 0.f;

    #pragma unroll 1
    for (int ks = 0; ks < 16; ks++) {
        __syncthreads();   // all warps done reading buf[(ks+1)&1] (from iter ks-1)
        if (ks + 1 < 16) issue_tile(su, xg, wbg, ks + 1, (ks + 1) & 1, tid);
        cp_commit();
        cp_wait<1>();      // tile ks landed (newest group may stay in flight)
        __syncthreads();

        const uint32_t xs  = su + BUF(ks & 1);
        const uint32_t wbs = xs + 16384;
        #pragma unroll
        for (int kk = 0; kk < 4; kk++) {
            uint32_t a[4][4], b[4][2];
            #pragma unroll
            for (int mt = 0; mt < 4; mt++) {
                int row = warp_m * 64 + mt * 16 + ((lane >> 3) & 1) * 8 + (lane & 7);
                int ch  = kk * 2 + (lane >> 4);
                ldsm4(a[mt][0], a[mt][1], a[mt][2], a[mt][3],
                      xs + row * 128 + ((ch ^ (row & 7)) << 4));
            }
            #pragma unroll
            for (int p = 0; p < 2; p++) {
                int row = warp_n * 32 + p * 16 + (lane >> 4) * 8 + (lane & 7);
                int ch  = kk * 2 + ((lane >> 3) & 1);
                ldsm4(b[2*p][0], b[2*p][1], b[2*p+1][0], b[2*p+1][1],
                      wbs + row * 128 + ((ch ^ (row & 7)) << 4));
            }
            #pragma unroll
            for (int mt = 0; mt < 4; mt++)
                #pragma unroll
                for (int nt = 0; nt < 4; nt++)
                    mma16(acc[mt][nt], a[mt], b[nt]);
        }
    }

    // epilogue: y = acc + bb -> ysw (fp16 swizzled; overlays staging buf0 —
    // safe: last compute used buf1, and the ks=15 barrier drained buf0 readers)
    #pragma unroll
    for (int mt = 0; mt < 4; mt++) {
        #pragma unroll
        for (int nt = 0; nt < 4; nt++) {
            int c0 = warp_n * 32 + nt * 8 + 2 * (lane & 3);
            int r0 = warp_m * 64 + mt * 16 + (lane >> 2);
            float bx0 = bbs[c0], bx1 = bbs[c0 + 1];
            uint32_t sw0 = (((c0 >> 3) ^ (r0 & 7)) << 4) + ((c0 * 2) & 15);
            uint32_t sw1 = (((c0 >> 3) ^ ((r0 + 8) & 7)) << 4) + ((c0 * 2) & 15);
            *(uint32_t*)(smem + YSW_OFF + r0 * 256 + sw0) =
                h2u(__floats2half2_rn(acc[mt][nt][0] + bx0, acc[mt][nt][1] + bx1));
            *(uint32_t*)(smem + YSW_OFF + (r0 + 8) * 256 + sw1) =
                h2u(__floats2half2_rn(acc[mt][nt][2] + bx0, acc[mt][nt][3] + bx1));
        }
    }
    cp_wait<0>();      // W seed-0 images resident
    __syncthreads();   // ysw visible; all warps past compute(15) before h writes

    const uint32_t ysw_b = su + YSW_OFF;
    const uint32_t h_b   = su + H_OFF;
    const uint32_t w1b   = su + W_OFF;
    const uint32_t w2b   = su + W_OFF + 16384;

    // ================= per-seed MLP + blend =================
    #pragma unroll 1
    for (int sl = 0; sl < 2; sl++) {
        const int sg = bx * 2 + sl;

        if (sl) {   // load seed-1 W images (seed-0 stage B done, synced below)
            issue_w(su, sg, tid);
            cp_commit();
            cp_wait<0>();
            __syncthreads();
        }

        // ---- stage A: h = relu(y @ W1 + b1)   M=128 N=128 K=64 ----
        {
            float accA[4][4][4];
            #pragma unroll
            for (int mt = 0; mt < 4; mt++)
                #pragma unroll
                for (int nt = 0; nt < 4; nt++)
                    #pragma unroll
                    for (int q = 0; q < 4; q++) accA[mt][nt][q] = 0.f;

            #pragma unroll
            for (int kk = 0; kk < 4; kk++) {
                uint32_t a[4][4], b[4][2];
                #pragma unroll
                for (int mt = 0; mt < 4; mt++) {
                    int row = warp_m * 64 + mt * 16 + ((lane >> 3) & 1) * 8 + (lane & 7);
                    int ch  = sl * 8 + kk * 2 + (lane >> 4);
                    ldsm4(a[mt][0], a[mt][1], a[mt][2], a[mt][3],
                          ysw_b + row * 256 + ((ch ^ (row & 7)) << 4));
                }
                #pragma unroll
                for (int p = 0; p < 2; p++) {
                    int row = warp_n * 32 + p * 16 + (lane >> 4) * 8 + (lane & 7);
                    int ch  = kk * 2 + ((lane >> 3) & 1);
                    ldsm4(b[2*p][0], b[2*p][1], b[2*p+1][0], b[2*p+1][1],
                          w1b + row * 128 + ((ch ^ (row & 7)) << 4));
                }
                #pragma unroll
                for (int mt = 0; mt < 4; mt++)
                    #pragma unroll
                    for (int nt = 0; nt < 4; nt++)
                        mma16(accA[mt][nt], a[mt], b[nt]);
            }

            // bias + relu -> h (fp16 swizzled)
            #pragma unroll
            for (int mt = 0; mt < 4; mt++) {
                #pragma unroll
                for (int nt = 0; nt < 4; nt++) {
                    int h0 = warp_n * 32 + nt * 8 + 2 * (lane & 3);
                    int r0 = warp_m * 64 + mt * 16 + (lane >> 2);
                    float2 b1v = *(const float2*)&b1[sg * 128 + h0];
                    float v0 = fmaxf(accA[mt][nt][0] + b1v.x, 0.f);
                    float v1 = fmaxf(accA[mt][nt][1] + b1v.y, 0.f);
                    float v2 = fmaxf(accA[mt][nt][2] + b1v.x, 0.f);
                    float v3 = fmaxf(accA[mt][nt][3] + b1v.y, 0.f);
                    uint32_t sw0 = (((h0 >> 3) ^ (r0 & 7)) << 4) + ((h0 * 2) & 15);
                    uint32_t sw1 = (((h0 >> 3) ^ ((r0 + 8) & 7)) << 4) + ((h0 * 2) & 15);
                    *(uint32_t*)(smem + H_OFF + r0 * 256 + sw0) =
                        h2u(__floats2half2_rn(v0, v1));
                    *(uint32_t*)(smem + H_OFF + (r0 + 8) * 256 + sw1) =
                        h2u(__floats2half2_rn(v2, v3));
                }
            }
        }
        __syncthreads();

        // ---- stage B: bp = h @ W2 + b2; blend with fp16 y; store ----
        {
            float accB[4][2][4];
            #pragma unroll
            for (int mt = 0; mt < 4; mt++)
                #pragma unroll
                for (int nt = 0; nt < 2; nt++)
                    #pragma unroll
                    for (int q = 0; q < 4; q++) accB[mt][nt][q] = 0.f;

            #pragma unroll 2
            for (int kk = 0; kk < 8; kk++) {
                uint32_t a[4][4], b[2][2];
                #pragma unroll
                for (int mt = 0; mt < 4; mt++) {
                    int row = warp_m * 64 + mt * 16 + ((lane >> 3) & 1) * 8 + (lane & 7);
                    int ch  = kk * 2 + (lane >> 4);
                    ldsm4(a[mt][0], a[mt][1], a[mt][2], a[mt][3],
                          h_b + row * 256 + ((ch ^ (row & 7)) << 4));
                }
                {
                    int row = warp_n * 16 + (lane >> 4) * 8 + (lane & 7);
                    int ch  = kk * 2 + ((lane >> 3) & 1);
                    ldsm4(b[0][0], b[0][1], b[1][0], b[1][1],
                          w2b + row * 256 + ((ch ^ (row & 7)) << 4));
                }
                #pragma unroll
                for (int mt = 0; mt < 4; mt++)
                    #pragma unroll
                    for (int nt = 0; nt < 2; nt++)
                        mma16(accB[mt][nt], a[mt], b[nt]);
            }

            const float aw  = alpha[sg] * (active[sg] != 0 ? 1.f : 0.f);
            const float omw = 1.f - aw;
            #pragma unroll
            for (int mt = 0; mt < 4; mt++) {
                #pragma unroll
                for (int nt = 0; nt < 2; nt++) {
                    int c0 = warp_n * 16 + nt * 8 + 2 * (lane & 3);
                    int cy = sl * 64 + c0;
                    int r0 = warp_m * 64 + mt * 16 + (lane >> 2);
                    float2 b2v = *(const float2*)&b2[sg * 64 + c0];

                    __half2 hy0 = *(const __half2*)(smem + YSW_OFF + r0 * 256 +
                                   (((cy >> 3) ^ (r0 & 7)) << 4) + ((cy * 2) & 15));
                    float2 y0 = __half22float2(hy0);
                    *(float2*)&out[(size_t)(row0 + r0) * D_OUT + bx * 128 + cy] =
                        make_float2(omw * y0.x + aw * (accB[mt][nt][0] + b2v.x),
                                    omw * y0.y + aw * (accB[mt][nt][1] + b2v.y));

                    __half2 hy1 = *(const __half2*)(smem + YSW_OFF + (r0 + 8) * 256 +
                                   (((cy >> 3) ^ ((r0 + 8) & 7)) << 4) + ((cy * 2) & 15));
                    float2 y1 = __half22float2(hy1);
                    *(float2*)&out[(size_t)(row0 + r0 + 8) * D_OUT + bx * 128 + cy] =
                        make_float2(omw * y1.x + aw * (accB[mt][nt][2] + b2v.x),
                                    omw * y1.y + aw * (accB[mt][nt][3] + b2v.y));
                }
            }
        }
        __syncthreads();
    }
}

extern "C" void kernel_launch(void* const* d_in, const int* in_sizes, int n_in,
                              void* d_out, int out_size)
{
    const float* x      = (const float*)d_in[0];
    const float* Wb     = (const float*)d_in[1];
    const float* bb     = (const float*)d_in[2];
    const float* W1     = (const float*)d_in[3];
    const float* b1     = (const float*)d_in[4];
    const float* W2     = (const float*)d_in[5];
    const float* b2     = (const float*)d_in[6];
    const float* alpha  = (const float*)d_in[7];
    const int*   active = (const int*)d_in[8];
    float* out = (float*)d_out;

    prep_kernel<<<1024, 256>>>(x, Wb, W1, W2);

    cudaFuncSetAttribute(kasmina_main_kernel,
                         cudaFuncAttributeMaxDynamicSharedMemorySize, SMEM_TOTAL);
    dim3 grid(32, 64);
    kasmina_main_kernel<<<grid, NTH, SMEM_TOTAL>>>(
        bb, b1, b2, alpha, active, out);
}

// round 8
// speedup vs baseline: 9.3991x; 1.0176x over previous
#include <cuda_runtime.h>
#include <cuda_fp16.h>
#include <cstdint>

#define NTH    256
#define D_IN   1024
#define D_OUT  4096
#define XN     (8192 * 1024)
#define WBN    (4096 * 1024)

__device__ __half g_xh[XN];           // x  as fp16
__device__ __half g_wbh[WBN];         // Wb as fp16
__device__ __half g_w1img[64 * 8192]; // W1 pre-swizzled smem images (16KB/seed)
__device__ __half g_w2img[64 * 8192]; // W2 pre-swizzled smem images

// ---------------- smem layout (bytes) ----------------
// phase 1: 3 staging buffers 32KB (x 16KB + wb 16KB each), k-tile=64
// phase 2 overlays staging:
//   ysw fp16 [128][128] swz  buf0:      0 .. 32767
//   h   fp16 [128][128] swz  buf1:  32768 .. 65535
//   W   (W1 16KB + W2 16KB)  buf2:  65536 .. 98303
//   bbs fp32 [128]                  98304 .. 98815
#define BUF(i)   ((i) * 32768)
#define YSW_OFF  0
#define H_OFF    32768
#define W_OFF    65536
#define BBS_OFF  98304
#define SMEM_TOTAL 98816

__device__ __forceinline__ uint32_t h2u(__half2 h) {
    return *reinterpret_cast<uint32_t*>(&h);
}
__device__ __forceinline__ void cpa16(uint32_t dst, const void* src) {
    asm volatile("cp.async.cg.shared.global [%0], [%1], 16;"
                 :: "r"(dst), "l"(src) : "memory");
}
__device__ __forceinline__ void cp_commit() {
    asm volatile("cp.async.commit_group;" ::: "memory");
}
template <int N>
__device__ __forceinline__ void cp_wait() {
    asm volatile("cp.async.wait_group %0;" :: "n"(N) : "memory");
}
__device__ __forceinline__ void ldsm4(uint32_t& r0, uint32_t& r1, uint32_t& r2,
                                      uint32_t& r3, uint32_t addr) {
    asm volatile("ldmatrix.sync.aligned.m8n8.x4.shared.b16 {%0,%1,%2,%3}, [%4];"
                 : "=r"(r0), "=r"(r1), "=r"(r2), "=r"(r3) : "r"(addr));
}
__device__ __forceinline__ void mma16(float* c, const uint32_t* a, const uint32_t* b) {
    asm volatile("mma.sync.aligned.m16n8k16.row.col.f32.f16.f16.f32 "
                 "{%0,%1,%2,%3},{%4,%5,%6,%7},{%8,%9},{%0,%1,%2,%3};"
                 : "+f"(c[0]), "+f"(c[1]), "+f"(c[2]), "+f"(c[3])
                 : "r"(a[0]), "r"(a[1]), "r"(a[2]), "r"(a[3]),
                   "r"(b[0]), "r"(b[1]));
}

// ============== prep: fp16 conversions + pre-swizzled W images ==============
__global__ void prep_kernel(const float* __restrict__ x,  const float* __restrict__ Wb,
                            const float* __restrict__ W1, const float* __restrict__ W2)
{
    const int tid = blockIdx.x * blockDim.x + threadIdx.x;
    const int nth = gridDim.x * blockDim.x;

    for (int i = tid; i < XN / 4; i += nth) {
        float4 v = ((const float4*)x)[i];
        ((uint2*)g_xh)[i] = make_uint2(h2u(__floats2half2_rn(v.x, v.y)),
                                       h2u(__floats2half2_rn(v.z, v.w)));
    }
    for (int i = tid; i < WBN / 4; i += nth) {
        float4 v = ((const float4*)Wb)[i];
        ((uint2*)g_wbh)[i] = make_uint2(h2u(__floats2half2_rn(v.x, v.y)),
                                        h2u(__floats2half2_rn(v.z, v.w)));
    }
    // W1 [s][c][h] -> image [h][c], row=64 fp16=128B, swizzled
    for (int i = tid; i < 64 * 64 * 128; i += nth) {
        int s = i >> 13, c = (i >> 7) & 63, h = i & 127;
        int off = h * 64 + ((((c >> 3) ^ (h & 7)) << 3) | (c & 7));
        g_w1img[s * 8192 + off] = __float2half(W1[i]);
    }
    // W2 [s][h][c] -> image [c][h], row=128 fp16=256B, swizzled
    for (int i = tid; i < 64 * 128 * 64; i += nth) {
        int s = i >> 13, h = (i >> 6) & 127, c = i & 63;
        int off = c * 128 + ((((h >> 3) ^ (c & 7)) << 3) | (h & 7));
        g_w2img[s * 8192 + off] = __float2half(W2[i]);
    }
}

// stage one k-tile (k=64): x[128x64]h + wb[128x64]h, both 16KB, 128B rows
__device__ __forceinline__ void issue_tile(uint32_t su, const __half* xg,
                                           const __half* wbg, int kt, int b, int tid)
{
    const int k0 = kt * 64;
    #pragma unroll
    for (int i = 0; i < 4; i++) {
        int idx = tid + i * NTH;
        int r = idx >> 3, c4 = idx & 7;
        cpa16(su + BUF(b) + r * 128 + ((c4 ^ (r & 7)) << 4),
              xg + (size_t)r * D_IN + k0 + c4 * 8);
    }
    #pragma unroll
    for (int i = 0; i < 4; i++) {
        int idx = tid + i * NTH;
        int n = idx >> 3, c4 = idx & 7;
        cpa16(su + BUF(b) + 16384 + n * 128 + ((c4 ^ (n & 7)) << 4),
              wbg + (size_t)n * D_IN + k0 + c4 * 8);
    }
}

// 16KB image loads (1024 x 16B chunks, 4 per thread)
__device__ __forceinline__ void issue_w1(uint32_t su, int sg, int tid) {
    const __half* src = g_w1img + (size_t)sg * 8192;
    #pragma unroll
    for (int i = 0; i < 4; i++) {
        int c = tid + i * NTH;
        cpa16(su + W_OFF + c * 16, src + c * 8);
    }
}
__device__ __forceinline__ void issue_w2(uint32_t su, int sg, int tid) {
    const __half* src = g_w2img + (size_t)sg * 8192;
    #pragma unroll
    for (int i = 0; i < 4; i++) {
        int c = tid + i * NTH;
        cpa16(su + W_OFF + 16384 + c * 16, src + c * 8);
    }
}

__global__ __launch_bounds__(NTH, 2)
void kasmina_main_kernel(const float* __restrict__ bb,
                         const float* __restrict__ b1,
                         const float* __restrict__ b2,
                         const float* __restrict__ alpha,
                         const int*   __restrict__ active,
                         float* __restrict__ out)
{
    extern __shared__ char smem[];
    const uint32_t su = (uint32_t)__cvta_generic_to_shared(smem);
    float* bbs = (float*)(smem + BBS_OFF);

    const int bx   = blockIdx.x;          // out cols [bx*128, bx*128+128)
    const int row0 = blockIdx.y * 128;

    const int tid    = threadIdx.x;
    const int lane   = tid & 31;
    const int wid    = tid >> 5;
    const int warp_m = wid & 1;
    const int warp_n = wid >> 1;

    const __half* xg  = g_xh  + (size_t)row0 * D_IN;
    const __half* wbg = g_wbh + (size_t)(bx * 128) * D_IN;

    if (tid < 128) bbs[tid] = bb[bx * 128 + tid];

    // prologue: tiles 0,1
    issue_tile(su, xg, wbg, 0, 0, tid);  cp_commit();
    issue_tile(su, xg, wbg, 1, 1, tid);  cp_commit();

    // ================= base GEMM: 16 k-tiles, 3-buffer, 1 barrier/tile =================
    float acc[4][4][4];
    #pragma unroll
    for (int mt = 0; mt < 4; mt++)
        #pragma unroll
        for (int nt = 0; nt < 4; nt++)
            #pragma unroll
            for (int q = 0; q < 4; q++) acc[mt][nt][q] = 0.f;

    #pragma unroll 1
    for (int ks = 0; ks < 16; ks++) {
        cp_wait<1>();      // tile ks landed (one newer group may be in flight)
        __syncthreads();   // + every warp finished reading buf[(ks-1)%3]
        if (ks + 2 < 16) issue_tile(su, xg, wbg, ks + 2, (ks + 2) % 3, tid);
        cp_commit();

        const uint32_t xs  = su + BUF(ks % 3);
        const uint32_t wbs = xs + 16384;
        #pragma unroll
        for (int kk = 0; kk < 4; kk++) {
            uint32_t a[4][4], b[4][2];
            #pragma unroll
            for (int mt = 0; mt < 4; mt++) {
                int row = warp_m * 64 + mt * 16 + ((lane >> 3) & 1) * 8 + (lane & 7);
                int ch  = kk * 2 + (lane >> 4);
                ldsm4(a[mt][0], a[mt][1], a[mt][2], a[mt][3],
                      xs + row * 128 + ((ch ^ (row & 7)) << 4));
            }
            #pragma unroll
            for (int p = 0; p < 2; p++) {
                int row = warp_n * 32 + p * 16 + (lane >> 4) * 8 + (lane & 7);
                int ch  = kk * 2 + ((lane >> 3) & 1);
                ldsm4(b[2*p][0], b[2*p][1], b[2*p+1][0], b[2*p+1][1],
                      wbs + row * 128 + ((ch ^ (row & 7)) << 4));
            }
            #pragma unroll
            for (int mt = 0; mt < 4; mt++)
                #pragma unroll
                for (int nt = 0; nt < 4; nt++)
                    mma16(acc[mt][nt], a[mt], b[nt]);
        }
    }
    __syncthreads();   // all warps past compute(15); buf0/buf2 free for reuse

    // prefetch seed-0 W images into buf2 (overlaps epilogue)
    issue_w1(su, bx * 2, tid);
    issue_w2(su, bx * 2, tid);
    cp_commit();

    // epilogue: y = acc + bb -> ysw (fp16 swizzled, overlays buf0)
    #pragma unroll
    for (int mt = 0; mt < 4; mt++) {
        #pragma unroll
        for (int nt = 0; nt < 4; nt++) {
            int c0 = warp_n * 32 + nt * 8 + 2 * (lane & 3);
            int r0 = warp_m * 64 + mt * 16 + (lane >> 2);
            float bx0 = bbs[c0], bx1 = bbs[c0 + 1];
            uint32_t sw0 = (((c0 >> 3) ^ (r0 & 7)) << 4) + ((c0 * 2) & 15);
            uint32_t sw1 = (((c0 >> 3) ^ ((r0 + 8) & 7)) << 4) + ((c0 * 2) & 15);
            *(uint32_t*)(smem + YSW_OFF + r0 * 256 + sw0) =
                h2u(__floats2half2_rn(acc[mt][nt][0] + bx0, acc[mt][nt][1] + bx1));
            *(uint32_t*)(smem + YSW_OFF + (r0 + 8) * 256 + sw1) =
                h2u(__floats2half2_rn(acc[mt][nt][2] + bx0, acc[mt][nt][3] + bx1));
        }
    }
    cp_wait<0>();      // W seed-0 images resident
    __syncthreads();   // ysw visible everywhere

    const uint32_t ysw_b = su + YSW_OFF;
    const uint32_t h_b   = su + H_OFF;
    const uint32_t w1b   = su + W_OFF;
    const uint32_t w2b   = su + W_OFF + 16384;

    // ================= per-seed MLP + blend (W prefetch pipelined) =================
    #pragma unroll 1
    for (int sl = 0; sl < 2; sl++) {
        const int sg = bx * 2 + sl;

        // ---- stage A: h = relu(y @ W1 + b1)   M=128 N=128 K=64 ----
        {
            float accA[4][4][4];
            #pragma unroll
            for (int mt = 0; mt < 4; mt++)
                #pragma unroll
                for (int nt = 0; nt < 4; nt++)
                    #pragma unroll
                    for (int q = 0; q < 4; q++) accA[mt][nt][q] = 0.f;

            #pragma unroll
            for (int kk = 0; kk < 4; kk++) {
                uint32_t a[4][4], b[4][2];
                #pragma unroll
                for (int mt = 0; mt < 4; mt++) {
                    int row = warp_m * 64 + mt * 16 + ((lane >> 3) & 1) * 8 + (lane & 7);
                    int ch  = sl * 8 + kk * 2 + (lane >> 4);
                    ldsm4(a[mt][0], a[mt][1], a[mt][2], a[mt][3],
                          ysw_b + row * 256 + ((ch ^ (row & 7)) << 4));
                }
                #pragma unroll
                for (int p = 0; p < 2; p++) {
                    int row = warp_n * 32 + p * 16 + (lane >> 4) * 8 + (lane & 7);
                    int ch  = kk * 2 + ((lane >> 3) & 1);
                    ldsm4(b[2*p][0], b[2*p][1], b[2*p+1][0], b[2*p+1][1],
                          w1b + row * 128 + ((ch ^ (row & 7)) << 4));
                }
                #pragma unroll
                for (int mt = 0; mt < 4; mt++)
                    #pragma unroll
                    for (int nt = 0; nt < 4; nt++)
                        mma16(accA[mt][nt], a[mt], b[nt]);
            }

            // bias + relu -> h (fp16 swizzled, buf1)
            #pragma unroll
            for (int mt = 0; mt < 4; mt++) {
                #pragma unroll
                for (int nt = 0; nt < 4; nt++) {
                    int h0 = warp_n * 32 + nt * 8 + 2 * (lane & 3);
                    int r0 = warp_m * 64 + mt * 16 + (lane >> 2);
                    float2 b1v = *(const float2*)&b1[sg * 128 + h0];
                    float v0 = fmaxf(accA[mt][nt][0] + b1v.x, 0.f);
                    float v1 = fmaxf(accA[mt][nt][1] + b1v.y, 0.f);
                    float v2 = fmaxf(accA[mt][nt][2] + b1v.x, 0.f);
                    float v3 = fmaxf(accA[mt][nt][3] + b1v.y, 0.f);
                    uint32_t sw0 = (((h0 >> 3) ^ (r0 & 7)) << 4) + ((h0 * 2) & 15);
                    uint32_t sw1 = (((h0 >> 3) ^ ((r0 + 8) & 7)) << 4) + ((h0 * 2) & 15);
                    *(uint32_t*)(smem + H_OFF + r0 * 256 + sw0) =
                        h2u(__floats2half2_rn(v0, v1));
                    *(uint32_t*)(smem + H_OFF + (r0 + 8) * 256 + sw1) =
                        h2u(__floats2half2_rn(v2, v3));
                }
            }
        }

        if (sl == 1) cp_wait<0>();   // W2 of seed 1 resident before its stage B
        __syncthreads();             // h visible; (sl==0): W1-slot reads complete

        if (sl == 0) {               // W1 of seed 1 streams in during stage B
            issue_w1(su, sg + 1, tid);
            cp_commit();
        }

        // ---- stage B: bp = h @ W2 + b2; blend with fp16 y; store ----
        {
            float accB[4][2][4];
            #pragma unroll
            for (int mt = 0; mt < 4; mt++)
                #pragma unroll
                for (int nt = 0; nt < 2; nt++)
                    #pragma unroll
                    for (int q = 0; q < 4; q++) accB[mt][nt][q] = 0.f;

            #pragma unroll 2
            for (int kk = 0; kk < 8; kk++) {
                uint32_t a[4][4], b[2][2];
                #pragma unroll
                for (int mt = 0; mt < 4; mt++) {
                    int row = warp_m * 64 + mt * 16 + ((lane >> 3) & 1) * 8 + (lane & 7);
                    int ch  = kk * 2 + (lane >> 4);
                    ldsm4(a[mt][0], a[mt][1], a[mt][2], a[mt][3],
                          h_b + row * 256 + ((ch ^ (row & 7)) << 4));
                }
                {
                    int row = warp_n * 16 + (lane >> 4) * 8 + (lane & 7);
                    int ch  = kk * 2 + ((lane >> 3) & 1);
                    ldsm4(b[0][0], b[0][1], b[1][0], b[1][1],
                          w2b + row * 256 + ((ch ^ (row & 7)) << 4));
                }
                #pragma unroll
                for (int mt = 0; mt < 4; mt++)
                    #pragma unroll
                    for (int nt = 0; nt < 2; nt++)
                        mma16(accB[mt][nt], a[mt], b[nt]);
            }

            const float aw  = alpha[sg] * (active[sg] != 0 ? 1.f : 0.f);
            const float omw = 1.f - aw;
            #pragma unroll
            for (int mt = 0; mt < 4; mt++) {
                #pragma unroll
                for (int nt = 0; nt < 2; nt++) {
                    int c0 = warp_n * 16 + nt * 8 + 2 * (lane & 3);
                    int cy = sl * 64 + c0;
                    int r0 = warp_m * 64 + mt * 16 + (lane >> 2);
                    float2 b2v = *(const float2*)&b2[sg * 64 + c0];

                    __half2 hy0 = *(const __half2*)(smem + YSW_OFF + r0 * 256 +
                                   (((cy >> 3) ^ (r0 & 7)) << 4) + ((cy * 2) & 15));
                    float2 y0 = __half22float2(hy0);
                    *(float2*)&out[(size_t)(row0 + r0) * D_OUT + bx * 128 + cy] =
                        make_float2(omw * y0.x + aw * (accB[mt][nt][0] + b2v.x),
                                    omw * y0.y + aw * (accB[mt][nt][1] + b2v.y));

                    __half2 hy1 = *(const __half2*)(smem + YSW_OFF + (r0 + 8) * 256 +
                                   (((cy >> 3) ^ ((r0 + 8) & 7)) << 4) + ((cy * 2) & 15));
                    float2 y1 = __half22float2(hy1);
                    *(float2*)&out[(size_t)(row0 + r0 + 8) * D_OUT + bx * 128 + cy] =
                        make_float2(omw * y1.x + aw * (accB[mt][nt][2] + b2v.x),
                                    omw * y1.y + aw * (accB[mt][nt][3] + b2v.y));
                }
            }
        }
        __syncthreads();   // stage B done; W2 slot free

        if (sl == 0) {     // W2 of seed 1 streams in (W1 already committed)
            issue_w2(su, sg + 1, tid);
            cp_commit();
        }
    }
}

extern "C" void kernel_launch(void* const* d_in, const int* in_sizes, int n_in,
                              void* d_out, int out_size)
{
    const float* x      = (const float*)d_in[0];
    const float* Wb     = (const float*)d_in[1];
    const float* bb     = (const float*)d_in[2];
    const float* W1     = (const float*)d_in[3];
    const float* b1     = (const float*)d_in[4];
    const float* W2     = (const float*)d_in[5];
    const float* b2     = (const float*)d_in[6];
    const float* alpha  = (const float*)d_in[7];
    const int*   active = (const int*)d_in[8];
    float* out = (float*)d_out;

    prep_kernel<<<1024, 256>>>(x, Wb, W1, W2);

    cudaFuncSetAttribute(kasmina_main_kernel,
                         cudaFuncAttributeMaxDynamicSharedMemorySize, SMEM_TOTAL);
    dim3 grid(32, 64);
    kasmina_main_kernel<<<grid, NTH, SMEM_TOTAL>>>(
        bb, b1, b2, alpha, active, out);
}